// round 15
// baseline (speedup 1.0000x reference)
#include <cuda_runtime.h>
#include <cuda_fp16.h>
#include <math_constants.h>
#include <cstdint>

#define C 128
#define H 96
#define W 128
#define P (H * W)            // 12288
#define NSPL 3
#define NCHUNK (P / NSPL)    // 4096
#define NT (NCHUNK / 256)    // 16 N-tiles (of 256) per CTA
#define NCK (NT * 2)         // 32 chunks: (tile, khalf)
#define IDESC 0x8400010u     // f32 accum, fp16 x fp16, N=256, M=128 (cg1)
#define NTHREADS 416         // warps 0-7 consumers, 8-11 loaders, 12 MMA

// tcgen05 is an arch-SPECIFIC feature: only valid when compiling for sm_103a.
#if defined(__CUDA_ARCH__) && defined(__CUDA_ARCH_FEAT_SM103_ALL)
#define HAS_TC 1
#else
#define HAS_TC 0
#endif

// ---------------- device globals (scratch; no allocation allowed) ----------
__device__ unsigned long long g_best[P];
__device__ unsigned g_cnt[P / 128];      // per-m-tile completion counters
__device__ __half g_Bsp[2ull * P * C];   // [lvl][pixel][channel] (B only)

// ---------------- smem layout (dynamic) ------------------------------------
#define SM_TMEM  0
#define MB_FULL  16      // 2 x 8B  (loaders -> MMA, count=128)
#define MB_EMPTY 32      // 2 x 8B  (MMA commit -> loaders AND consumers, count=1)
#define MB_E     64      // 2 x 8B  (consumers -> MMA, count=8)
#define SM_LAST  112     // 4B flag: this CTA decodes its m-tile
#define SM_B     1024                     // 2 bufs x 65536 (2 lvls x 256rows x 128B)
#define SM_A     (SM_B + 2 * 65536)       // 2 lvls x 32768
#define SMEM_TOTAL (SM_A + 2 * 32768)     // 197632 bytes

// TMEM: D double buffer at cols 0 / 256 (256 cols each).
#define TM_D 0

// ---------------- PTX helpers ----------------------------------------------
__device__ __forceinline__ uint32_t smem_u32(const void* p) {
    uint32_t a;
    asm("{ .reg .u64 t; cvta.to.shared.u64 t, %1; cvt.u32.u64 %0, t; }"
        : "=r"(a) : "l"(p));
    return a;
}
__device__ __forceinline__ uint32_t swz(uint32_t b) { return b ^ ((b >> 3) & 0x70); }
__device__ __forceinline__ uint32_t a_off(int m, int k) {
    // blocked atom layout: atom = 8 rows x 64 fp16 (1024B); 16 atom-rows x 2 atom-cols
    return ((uint32_t)((m >> 3) + (k >> 6) * 16)) * 1024u + (uint32_t)(m & 7) * 128u
         + (uint32_t)(k & 63) * 2u;
}
__device__ __forceinline__ uint64_t mk_desc(uint32_t addr) {
    // SW128, Blackwell version=1, LBO=1, SBO=64 (K-major)
    return ((uint64_t)2 << 61) | ((uint64_t)1 << 46) | ((uint64_t)64 << 32)
         | ((uint64_t)1 << 16) | ((addr >> 4) & 0x3FFF);
}

__device__ __forceinline__ void cp_async16(uint32_t dst, const void* src) {
    asm volatile("cp.async.cg.shared.global [%0], [%1], 16;"
                 :: "r"(dst), "l"(src) : "memory");
}
__device__ __forceinline__ void cp_commit() {
    asm volatile("cp.async.commit_group;" ::: "memory");
}
__device__ __forceinline__ void cp_wait0() {
    asm volatile("cp.async.wait_group 0;" ::: "memory");
}

__device__ __forceinline__ void mbar_init(uint32_t a, uint32_t n) {
#if HAS_TC
    asm volatile("mbarrier.init.shared.b64 [%0], %1;" :: "r"(a), "r"(n) : "memory");
#endif
}
__device__ __forceinline__ void mbar_arrive(uint32_t a) {
#if HAS_TC
    asm volatile("mbarrier.arrive.shared.b64 _, [%0];" :: "r"(a) : "memory");
#endif
}
__device__ __forceinline__ void tc_commit(uint32_t a) {
#if HAS_TC
    asm volatile("tcgen05.commit.cta_group::1.mbarrier::arrive::one.shared::cluster.b64 [%0];"
                 :: "r"(a) : "memory");
#endif
}
__device__ __forceinline__ void tc_fence_after()  {
#if HAS_TC
    asm volatile("tcgen05.fence::after_thread_sync;" ::: "memory");
#endif
}
__device__ __forceinline__ void tc_fence_before() {
#if HAS_TC
    asm volatile("tcgen05.fence::before_thread_sync;" ::: "memory");
#endif
}
__device__ __forceinline__ void tc_wait_ld() {
#if HAS_TC
    asm volatile("tcgen05.wait::ld.sync.aligned;" ::: "memory");
#endif
}
__device__ __forceinline__ void fence_async() {
#if HAS_TC
    asm volatile("fence.proxy.async.shared::cta;" ::: "memory");
#endif
}
__device__ __forceinline__ void tc_alloc(uint32_t dst, uint32_t ncols) {
#if HAS_TC
    asm volatile("tcgen05.alloc.cta_group::1.sync.aligned.shared::cta.b32 [%0], %1;"
                 :: "r"(dst), "r"(ncols) : "memory");
#endif
}
__device__ __forceinline__ void tc_dealloc(uint32_t tmem, uint32_t ncols) {
#if HAS_TC
    asm volatile("tcgen05.relinquish_alloc_permit.cta_group::1.sync.aligned;");
    asm volatile("tcgen05.dealloc.cta_group::1.sync.aligned.b32 %0, %1;"
                 :: "r"(tmem), "r"(ncols));
#endif
}
// Acquire wait (consumers: generic LDTM follows).
__device__ __forceinline__ void mbar_wait(uint32_t mbar, uint32_t parity) {
#if HAS_TC
    uint32_t done;
    asm volatile(
        "{\n\t.reg .pred p;\n\t"
        "mbarrier.try_wait.parity.acquire.cta.shared::cta.b64 p, [%1], %2;\n\t"
        "selp.b32 %0, 1, 0, p;\n\t}"
        : "=r"(done) : "r"(mbar), "r"(parity) : "memory");
    if (!done) {
        asm volatile(
            "{\n\t.reg .pred P1;\n\t"
            "W_%=:\n\t"
            "mbarrier.try_wait.parity.acquire.cta.shared::cta.b64 P1, [%0], %1, 0x989680;\n\t"
            "@P1 bra.uni D_%=;\n\t"
            "bra.uni W_%=;\n\t"
            "D_%=:\n\t}"
            :: "r"(mbar), "r"(parity) : "memory");
    }
#endif
}
// Relaxed wait (issuer/loaders: post-wait accesses are async-proxy only).
__device__ __forceinline__ void mbar_wait_rlx(uint32_t mbar, uint32_t parity) {
#if HAS_TC
    uint32_t done;
    asm volatile(
        "{\n\t.reg .pred p;\n\t"
        "mbarrier.try_wait.parity.relaxed.cta.shared::cta.b64 p, [%1], %2;\n\t"
        "selp.b32 %0, 1, 0, p;\n\t}"
        : "=r"(done) : "r"(mbar), "r"(parity) : "memory");
    if (!done) {
        asm volatile(
            "{\n\t.reg .pred P1;\n\t"
            "W_%=:\n\t"
            "mbarrier.try_wait.parity.relaxed.cta.shared::cta.b64 P1, [%0], %1, 0x989680;\n\t"
            "@P1 bra.uni D_%=;\n\t"
            "bra.uni W_%=;\n\t"
            "D_%=:\n\t}"
            :: "r"(mbar), "r"(parity) : "memory");
    }
#endif
}
__device__ __forceinline__ void mma_f16_ss(uint32_t d, uint64_t ad, uint64_t bd,
                                           uint32_t idesc, bool en) {
#if HAS_TC
    uint32_t e = en ? 1u : 0u;
    asm volatile(
        "{\n\t.reg .pred p;\n\tsetp.ne.u32 p, %5, 0;\n\t"
        "tcgen05.mma.cta_group::1.kind::f16 [%0], %1, %2, %3, {%4,%4,%4,%4}, p;\n\t}"
        :: "r"(d), "l"(ad), "l"(bd), "r"(idesc), "r"(0u), "r"(e) : "memory");
#endif
}
__device__ __forceinline__ void ldtm_x32(uint32_t* r, uint32_t ta) {
#if HAS_TC
    asm volatile(
        "tcgen05.ld.sync.aligned.32x32b.x32.b32 "
        "{%0,%1,%2,%3,%4,%5,%6,%7,%8,%9,%10,%11,%12,%13,%14,%15,"
        "%16,%17,%18,%19,%20,%21,%22,%23,%24,%25,%26,%27,%28,%29,%30,%31}, [%32];"
        : "=r"(r[0]), "=r"(r[1]), "=r"(r[2]), "=r"(r[3]), "=r"(r[4]), "=r"(r[5]),
          "=r"(r[6]), "=r"(r[7]), "=r"(r[8]), "=r"(r[9]), "=r"(r[10]), "=r"(r[11]),
          "=r"(r[12]), "=r"(r[13]), "=r"(r[14]), "=r"(r[15]), "=r"(r[16]), "=r"(r[17]),
          "=r"(r[18]), "=r"(r[19]), "=r"(r[20]), "=r"(r[21]), "=r"(r[22]), "=r"(r[23]),
          "=r"(r[24]), "=r"(r[25]), "=r"(r[26]), "=r"(r[27]), "=r"(r[28]), "=r"(r[29]),
          "=r"(r[30]), "=r"(r[31])
        : "r"(ta));
#endif
}

// ---------------- argmax packing -------------------------------------------
__device__ __forceinline__ unsigned long long pack_key(float v, int idx) {
    unsigned u = __float_as_uint(v);
    u = (u & 0x80000000u) ? ~u : (u | 0x80000000u);
    return ((unsigned long long)u << 14) | (unsigned)(0x3FFF - idx);
}

// ---------------- split fp32 -> 2 x fp16, transposed to [lvl][p][k] --------
// B ONLY (A is split in-kernel by corr's prologue). 64k x 32p tiles; 16B
// coalesced half stores. y==0 blocks also zero g_best and g_cnt.
__global__ void split_kernel(const float* __restrict__ in, __half* __restrict__ out) {
    __shared__ float tile[64][33];
    const int pB = blockIdx.x * 32, kB = blockIdx.y * 64;
    const int t = threadIdx.x;            // 256
    const int tx = t & 31, ty = t >> 5;   // load mapping

    if (blockIdx.y == 0) {
        if (ty == 0) g_best[pB + tx] = 0ULL;
        if (t == 0) g_cnt[blockIdx.x / 4] = 0u;   // 384 blocks -> 96 counters (idempotent)
    }

    #pragma unroll
    for (int r = 0; r < 64; r += 8)
        tile[ty + r][tx] = in[(size_t)(kB + ty + r) * P + pB + tx];
    __syncthreads();

    // Each thread: one pixel p, 8 consecutive k -> one 16B store per level.
    const int p = t >> 3;
    const int ko = (t & 7) * 8;
    __half h0[8], h1[8];
    #pragma unroll
    for (int i = 0; i < 8; i++) {
        float x = tile[ko + i][p];
        __half a = __float2half_rn(x);
        float r1 = x - __half2float(a);
        h0[i] = a;
        h1[i] = __float2half_rn(r1);
    }
    size_t base = (size_t)(pB + p) * C + kB + ko;
    *(uint4*)&out[base] = *(uint4*)h0;
    *(uint4*)&out[(size_t)P * C + base] = *(uint4*)h1;
}

// ---------------- main GEMM + fused argmax + fused decode ---------------------
// grid (96,3), 416 threads. Warps 0-7 consumers, 8-11 loaders, 12 MMA issuer.
// fp16 2-split, 3 products. SS-mode, N=256 dispatches, 2-deep 64KB B ring.
// A is split fp32->2xfp16 IN the prologue (no global round-trip). D-ready is
// inferred from EMPTY(buf1) commits; consumers release D TMEM right after the
// last LDTM. Last CTA per m-tile decodes flow in-place.
__global__ __launch_bounds__(NTHREADS, 1) void corr_kernel(const float* __restrict__ A32,
                                                           const float* __restrict__ B32,
                                                           float* __restrict__ out,
                                                           const int* __restrict__ sxp,
                                                           const int* __restrict__ syp,
                                                           int has_scale) {
    extern __shared__ char smem[];
    const int tid = threadIdx.x;
    const int mBase = blockIdx.x * 128;
    const int rBase0 = blockIdx.y * NCHUNK;

#if HAS_TC
    // ======================= tcgen05 path =====================================
    const uint32_t sb = smem_u32(smem);
    const int wid = tid >> 5;

    if (wid == 12) tc_alloc(sb + SM_TMEM, 512u);
    if (tid == 0) {
        #pragma unroll
        for (int b = 0; b < 2; b++) {
            mbar_init(sb + MB_FULL + 8 * b, 128);
            mbar_init(sb + MB_EMPTY + 8 * b, 1);
        }
        mbar_init(sb + MB_E + 0, 8);
        mbar_init(sb + MB_E + 8, 8);
    }

    // ---- A prologue, fused split: fp32 tile -> h0/h1 swizzled smem tiles ----
    // Phase 1: coalesced load of A fp32 tile [128k][128m] into padded temp
    // (reuses the B-ring region, which is untouched until after __syncthreads).
    {
        float* atile = (float*)(smem + SM_B);     // [128][132] padded
        for (int e = tid; e < 128 * 128; e += NTHREADS) {
            int k = e >> 7, m = e & 127;
            atile[k * 132 + m] = A32[(size_t)k * P + mBase + m];
        }
        __syncthreads();
        // Phase 2: split + 16B swizzled stores (m-fast lane mapping:
        // stride-4B smem reads; swizzle spreads stores across bank quads).
        for (int e = tid; e < 2048; e += NTHREADS) {
            int m = e & 127, kq = e >> 7;
            __half h0[8], h1[8];
            #pragma unroll
            for (int i = 0; i < 8; i++) {
                float x = atile[(kq * 8 + i) * 132 + m];
                h0[i] = __float2half_rn(x);
                h1[i] = __float2half_rn(x - __half2float(h0[i]));
            }
            uint32_t off = swz(a_off(m, kq * 8));
            *(uint4*)(smem + SM_A + off) = *(uint4*)h0;
            *(uint4*)(smem + SM_A + 32768 + off) = *(uint4*)h1;
        }
    }
    fence_async();
    __syncthreads();

    uint32_t tmem;
    asm volatile("ld.shared.b32 %0, [%1];" : "=r"(tmem) : "r"(sb + SM_TMEM));

    if (wid >= 8 && wid < 12) {
        // -------- loaders: stream B chunks (tile-of-256, khalf) via cp.async ----
        const int tl = tid - 256;
        const int kq = tl & 7;                  // K 16B-quarter, fixed per thread
        const int row0 = tl >> 3;               // base row (0..15), step 16
        const __half* gb0 = g_Bsp + (size_t)rBase0 * C + kq * 8;

        int eph[2] = {1, 1};   // producer phase trick: first waits pass
        for (int ck = 0; ck < NCK; ck++) {
            const int buf = ck & 1;
            mbar_wait_rlx(sb + MB_EMPTY + 8 * buf, (uint32_t)eph[buf]);
            eph[buf] ^= 1;

            const size_t coff = (size_t)(ck >> 1) * (256 * C) + (size_t)(ck & 1) * 64;
            const uint32_t dl = sb + SM_B + buf * 65536;
            #pragma unroll
            for (int l = 0; l < 2; l++) {
                const __half* g = gb0 + (size_t)l * P * C + coff;
                #pragma unroll
                for (int j = 0; j < 16; j++) {
                    const int n = row0 + 16 * j;
                    cp_async16(dl + l * 32768 + swz((uint32_t)n * 128u + (uint32_t)kq * 16u),
                               g + (size_t)n * C);
                }
            }
            cp_commit();
            cp_wait0();
            fence_async();
            mbar_arrive(sb + MB_FULL + 8 * buf);
        }
    } else if (tid == 384) {
        // -------- dedicated MMA issuer (single thread of warp 12) --------------
        int fph[2] = {0, 0};
        int Eph[2] = {0, 0};
        uint64_t adesc[2];
        adesc[0] = mk_desc(sb + SM_A);
        adesc[1] = mk_desc(sb + SM_A + 32768);
        const int sa[3]  = {0, 0, 1};   // products: h0h0, h0h1, h1h0
        const int sbl[3] = {0, 1, 0};

        for (int ck = 0; ck < NCK; ck++) {
            const int buf = ck & 1, t = ck >> 1, kc = ck & 1;
            mbar_wait_rlx(sb + MB_FULL + 8 * buf, (uint32_t)fph[buf]);
            fph[buf] ^= 1;
            if (kc == 0 && t >= 2) {
                mbar_wait_rlx(sb + MB_E + 8 * (t & 1), (uint32_t)Eph[t & 1]);
                Eph[t & 1] ^= 1;
                tc_fence_after();
            }
            const uint32_t dt = tmem + TM_D + (t & 1) * 256;
            const uint32_t bb = sb + SM_B + buf * 65536;
            #pragma unroll
            for (int pr = 0; pr < 3; pr++) {
                uint64_t ad = adesc[sa[pr]];
                uint64_t bd = mk_desc(bb + sbl[pr] * 32768);
                #pragma unroll
                for (int ks = 0; ks < 4; ks++) {
                    const int s = kc * 4 + ks;
                    mma_f16_ss(dt, ad + (uint64_t)((s >> 2) * 1024 + (s & 3) * 2),
                               bd + (uint64_t)(ks * 2), IDESC,
                               !(kc == 0 && pr == 0 && ks == 0));
                }
            }
            // Single commit per chunk: frees the B buffer AND (for kc==1, i.e.
            // buf 1) tells consumers tile t's D is complete.
            tc_commit(sb + MB_EMPTY + 8 * buf);
        }
    } else if (wid < 8) {
        // -------- consumers: 8 warps; warp w = subpartition (w&3),
        // column half (w>>2)*128 of the 256-wide tile. 4 argmax chains. --------
        // D-ready for tile t = (t+1)-th firing of EMPTY(buf1) -> parity t&1.
        const int sp   = wid & 3;           // TMEM subpartition (= wid%4, HW rule)
        const int half = wid >> 2;          // 128-col half of the tile
        const int lane = tid & 31;
        const uint32_t woff = ((uint32_t)sp << 21) + (uint32_t)half * 128u;

        float bv[4];
        int   bi[4];
        #pragma unroll
        for (int c4 = 0; c4 < 4; c4++) { bv[c4] = -CUDART_INF_F; bi[c4] = 0; }

        for (int t = 0; t < NT; t++) {
            mbar_wait(sb + MB_EMPTY + 8, (uint32_t)(t & 1));
            tc_fence_after();
            const uint32_t dt = tmem + TM_D + (t & 1) * 256 + woff;
            const int colbase = rBase0 + t * 256 + half * 128;

            // q = 0
            {
                uint32_t r0[32], r1[32];
                ldtm_x32(r0, dt);
                ldtm_x32(r1, dt + 32);
                tc_wait_ld();
                #pragma unroll
                for (int j = 0; j < 32; j++) {
                    float v = __uint_as_float(r0[j]);
                    int c4 = j & 3;
                    if (v > bv[c4]) { bv[c4] = v; bi[c4] = colbase + j; }
                }
                #pragma unroll
                for (int j = 0; j < 32; j++) {
                    float v = __uint_as_float(r1[j]);
                    int c4 = j & 3;
                    if (v > bv[c4]) { bv[c4] = v; bi[c4] = colbase + 32 + j; }
                }
            }
            // q = 1: release the D buffer right after the data is in registers.
            {
                uint32_t r0[32], r1[32];
                ldtm_x32(r0, dt + 64);
                ldtm_x32(r1, dt + 96);
                tc_wait_ld();
                tc_fence_before();
                if (lane == 0) mbar_arrive(sb + MB_E + 8 * (t & 1));
                #pragma unroll
                for (int j = 0; j < 32; j++) {
                    float v = __uint_as_float(r0[j]);
                    int c4 = j & 3;
                    if (v > bv[c4]) { bv[c4] = v; bi[c4] = colbase + 64 + j; }
                }
                #pragma unroll
                for (int j = 0; j < 32; j++) {
                    float v = __uint_as_float(r1[j]);
                    int c4 = j & 3;
                    if (v > bv[c4]) { bv[c4] = v; bi[c4] = colbase + 96 + j; }
                }
            }
        }

        // Merge the 4 chains via packed keys (ties -> smallest index), then atomic.
        unsigned long long k0 = pack_key(bv[0], bi[0]);
        unsigned long long k1 = pack_key(bv[1], bi[1]);
        unsigned long long k2 = pack_key(bv[2], bi[2]);
        unsigned long long k3 = pack_key(bv[3], bi[3]);
        unsigned long long ka = (k0 > k1) ? k0 : k1;
        unsigned long long kb = (k2 > k3) ? k2 : k3;
        unsigned long long kk = (ka > kb) ? ka : kb;
        atomicMax(&g_best[mBase + sp * 32 + lane], kk);
    }

    __syncthreads();

#else
    // ======================= fallback (non-'a' compile pass only) ============
    // Compile-only safety net: correct but slow; the sm_103a pass is what runs.
    for (int r = 0; r < 128; r++) {
        float bv = -CUDART_INF_F;
        int bi = rBase0;
        for (int c = rBase0 + tid; c < rBase0 + NCHUNK; c += NTHREADS) {
            float dot = 0.0f;
            for (int k = 0; k < C; k++)
                dot = fmaf(A32[(size_t)k * P + mBase + r], B32[(size_t)k * P + c], dot);
            if (dot > bv) { bv = dot; bi = c; }
        }
        atomicMax(&g_best[mBase + r], pack_key(bv, bi));
    }
    __syncthreads();
#endif

    // ---------- fused decode: last CTA (of NSPL) per m-tile decodes it -------
    int* lastf = (int*)(smem + SM_LAST);
    if (tid == 0) {
        __threadfence();
        unsigned old = atomicAdd(&g_cnt[blockIdx.x], 1u);
        *lastf = (old == NSPL - 1) ? 1 : 0;
    }
    __syncthreads();
    if (*lastf && tid < 128) {
        const int sx = has_scale ? sxp[0] : 4;
        const int sy = has_scale ? syp[0] : 4;
        const int p = mBase + tid;
        unsigned long long pk = __ldcg(&g_best[p]);
        int idx = 0x3FFF - (int)(pk & 0x3FFFULL);
        unsigned u = (unsigned)(pk >> 14);
        unsigned f = (u & 0x80000000u) ? (u ^ 0x80000000u) : ~u;
        float val = __uint_as_float(f);
        int h = p >> 7, w = p & 127;
        int i = idx >> 7, j = idx & 127;
        out[2 * p]     = (float)(w - j * sx);
        out[2 * p + 1] = (float)(h - i * sy);
        out[2 * P + p] = val;
    }

#if HAS_TC
    if ((tid >> 5) == 12) {
        uint32_t tmem2;
        asm volatile("ld.shared.b32 %0, [%1];" : "=r"(tmem2) : "r"(smem_u32(smem) + SM_TMEM));
        tc_dealloc(tmem2, 512u);
    }
#endif
}

// ---------------- launch -----------------------------------------------------
extern "C" void kernel_launch(void* const* d_in, const int* in_sizes, int n_in,
                              void* d_out, int out_size) {
    const float* A = (const float*)d_in[0];
    const float* B = (const float*)d_in[1];
    const int* sx = (n_in > 2) ? (const int*)d_in[2] : nullptr;
    const int* sy = (n_in > 3) ? (const int*)d_in[3] : nullptr;
    int has_scale = (n_in > 3) ? 1 : 0;

    cudaFuncSetAttribute(corr_kernel, cudaFuncAttributeMaxDynamicSharedMemorySize, SMEM_TOTAL);

    __half* dBs;
    cudaGetSymbolAddress((void**)&dBs, g_Bsp);

    dim3 sgrid(P / 32, C / 64), sblk(256);
    split_kernel<<<sgrid, sblk>>>(B, dBs);   // B only; also zeroes g_best/g_cnt

    dim3 grid(P / 128, NSPL);   // 96 x 3 = 288 CTAs
    corr_kernel<<<grid, NTHREADS, SMEM_TOTAL>>>(A, B, (float*)d_out, sx, sy, has_scale);
}

// round 16
// speedup vs baseline: 1.0215x; 1.0215x over previous
#include <cuda_runtime.h>
#include <cuda_fp16.h>
#include <math_constants.h>
#include <cstdint>

#define C 128
#define H 96
#define W 128
#define P (H * W)            // 12288
#define NSPL 3
#define NCHUNK (P / NSPL)    // 4096
#define NT (NCHUNK / 256)    // 16 N-tiles (of 256) per CTA
#define NCK (NT * 2)         // 32 chunks: (tile, khalf)
#define IDESC 0x8400010u     // f32 accum, fp16 x fp16, N=256, M=128 (cg1)
#define NTHREADS 416         // warps 0-7 consumers, 8-11 loaders, 12 MMA

// tcgen05 is an arch-SPECIFIC feature: only valid when compiling for sm_103a.
#if defined(__CUDA_ARCH__) && defined(__CUDA_ARCH_FEAT_SM103_ALL)
#define HAS_TC 1
#else
#define HAS_TC 0
#endif

// ---------------- device globals (scratch; no allocation allowed) ----------
__device__ unsigned long long g_best[P];
__device__ unsigned g_cnt[P / 128];      // per-m-tile completion counters
__device__ __half g_Bsp[2ull * P * C];   // [lvl][pixel][channel] (B only)

// ---------------- smem layout (dynamic) ------------------------------------
#define SM_TMEM  0
#define MB_FULL  16      // 2 x 8B  (loaders -> MMA, count=128)
#define MB_EMPTY 32      // 2 x 8B  (MMA commit -> loaders AND consumers, count=1)
#define MB_E     64      // 2 x 8B  (consumers -> MMA, count=8)
#define SM_LAST  112     // 4B flag: this CTA decodes its m-tile
#define SM_B     1024                     // 2 bufs x 65536 (2 lvls x 256rows x 128B)
#define SM_A     (SM_B + 2 * 65536)       // 2 lvls x 32768
#define SMEM_TOTAL (SM_A + 2 * 32768)     // 197632 bytes

// TMEM: D double buffer at cols 0 / 256 (256 cols each).
#define TM_D 0

// ---------------- PTX helpers ----------------------------------------------
__device__ __forceinline__ uint32_t smem_u32(const void* p) {
    uint32_t a;
    asm("{ .reg .u64 t; cvta.to.shared.u64 t, %1; cvt.u32.u64 %0, t; }"
        : "=r"(a) : "l"(p));
    return a;
}
__device__ __forceinline__ uint32_t swz(uint32_t b) { return b ^ ((b >> 3) & 0x70); }
__device__ __forceinline__ uint32_t a_off(int m, int k) {
    // blocked atom layout: atom = 8 rows x 64 fp16 (1024B); 16 atom-rows x 2 atom-cols
    return ((uint32_t)((m >> 3) + (k >> 6) * 16)) * 1024u + (uint32_t)(m & 7) * 128u
         + (uint32_t)(k & 63) * 2u;
}
__device__ __forceinline__ uint64_t mk_desc(uint32_t addr) {
    // SW128, Blackwell version=1, LBO=1, SBO=64 (K-major)
    return ((uint64_t)2 << 61) | ((uint64_t)1 << 46) | ((uint64_t)64 << 32)
         | ((uint64_t)1 << 16) | ((addr >> 4) & 0x3FFF);
}

__device__ __forceinline__ void cp_async16(uint32_t dst, const void* src) {
    asm volatile("cp.async.cg.shared.global [%0], [%1], 16;"
                 :: "r"(dst), "l"(src) : "memory");
}
__device__ __forceinline__ void cp_commit() {
    asm volatile("cp.async.commit_group;" ::: "memory");
}
__device__ __forceinline__ void cp_wait0() {
    asm volatile("cp.async.wait_group 0;" ::: "memory");
}

__device__ __forceinline__ void mbar_init(uint32_t a, uint32_t n) {
#if HAS_TC
    asm volatile("mbarrier.init.shared.b64 [%0], %1;" :: "r"(a), "r"(n) : "memory");
#endif
}
__device__ __forceinline__ void mbar_arrive(uint32_t a) {
#if HAS_TC
    asm volatile("mbarrier.arrive.shared.b64 _, [%0];" :: "r"(a) : "memory");
#endif
}
__device__ __forceinline__ void tc_commit(uint32_t a) {
#if HAS_TC
    asm volatile("tcgen05.commit.cta_group::1.mbarrier::arrive::one.shared::cluster.b64 [%0];"
                 :: "r"(a) : "memory");
#endif
}
__device__ __forceinline__ void tc_fence_after()  {
#if HAS_TC
    asm volatile("tcgen05.fence::after_thread_sync;" ::: "memory");
#endif
}
__device__ __forceinline__ void tc_fence_before() {
#if HAS_TC
    asm volatile("tcgen05.fence::before_thread_sync;" ::: "memory");
#endif
}
__device__ __forceinline__ void tc_wait_ld() {
#if HAS_TC
    asm volatile("tcgen05.wait::ld.sync.aligned;" ::: "memory");
#endif
}
__device__ __forceinline__ void fence_async() {
#if HAS_TC
    asm volatile("fence.proxy.async.shared::cta;" ::: "memory");
#endif
}
__device__ __forceinline__ void tc_alloc(uint32_t dst, uint32_t ncols) {
#if HAS_TC
    asm volatile("tcgen05.alloc.cta_group::1.sync.aligned.shared::cta.b32 [%0], %1;"
                 :: "r"(dst), "r"(ncols) : "memory");
#endif
}
__device__ __forceinline__ void tc_dealloc(uint32_t tmem, uint32_t ncols) {
#if HAS_TC
    asm volatile("tcgen05.relinquish_alloc_permit.cta_group::1.sync.aligned;");
    asm volatile("tcgen05.dealloc.cta_group::1.sync.aligned.b32 %0, %1;"
                 :: "r"(tmem), "r"(ncols));
#endif
}
// Acquire wait (consumers: generic LDTM follows).
__device__ __forceinline__ void mbar_wait(uint32_t mbar, uint32_t parity) {
#if HAS_TC
    uint32_t done;
    asm volatile(
        "{\n\t.reg .pred p;\n\t"
        "mbarrier.try_wait.parity.acquire.cta.shared::cta.b64 p, [%1], %2;\n\t"
        "selp.b32 %0, 1, 0, p;\n\t}"
        : "=r"(done) : "r"(mbar), "r"(parity) : "memory");
    if (!done) {
        asm volatile(
            "{\n\t.reg .pred P1;\n\t"
            "W_%=:\n\t"
            "mbarrier.try_wait.parity.acquire.cta.shared::cta.b64 P1, [%0], %1, 0x989680;\n\t"
            "@P1 bra.uni D_%=;\n\t"
            "bra.uni W_%=;\n\t"
            "D_%=:\n\t}"
            :: "r"(mbar), "r"(parity) : "memory");
    }
#endif
}
// Relaxed wait (issuer/loaders: post-wait accesses are async-proxy only).
__device__ __forceinline__ void mbar_wait_rlx(uint32_t mbar, uint32_t parity) {
#if HAS_TC
    uint32_t done;
    asm volatile(
        "{\n\t.reg .pred p;\n\t"
        "mbarrier.try_wait.parity.relaxed.cta.shared::cta.b64 p, [%1], %2;\n\t"
        "selp.b32 %0, 1, 0, p;\n\t}"
        : "=r"(done) : "r"(mbar), "r"(parity) : "memory");
    if (!done) {
        asm volatile(
            "{\n\t.reg .pred P1;\n\t"
            "W_%=:\n\t"
            "mbarrier.try_wait.parity.relaxed.cta.shared::cta.b64 P1, [%0], %1, 0x989680;\n\t"
            "@P1 bra.uni D_%=;\n\t"
            "bra.uni W_%=;\n\t"
            "D_%=:\n\t}"
            :: "r"(mbar), "r"(parity) : "memory");
    }
#endif
}
__device__ __forceinline__ void mma_f16_ss(uint32_t d, uint64_t ad, uint64_t bd,
                                           uint32_t idesc, bool en) {
#if HAS_TC
    uint32_t e = en ? 1u : 0u;
    asm volatile(
        "{\n\t.reg .pred p;\n\tsetp.ne.u32 p, %5, 0;\n\t"
        "tcgen05.mma.cta_group::1.kind::f16 [%0], %1, %2, %3, {%4,%4,%4,%4}, p;\n\t}"
        :: "r"(d), "l"(ad), "l"(bd), "r"(idesc), "r"(0u), "r"(e) : "memory");
#endif
}
__device__ __forceinline__ void ldtm_x32(uint32_t* r, uint32_t ta) {
#if HAS_TC
    asm volatile(
        "tcgen05.ld.sync.aligned.32x32b.x32.b32 "
        "{%0,%1,%2,%3,%4,%5,%6,%7,%8,%9,%10,%11,%12,%13,%14,%15,"
        "%16,%17,%18,%19,%20,%21,%22,%23,%24,%25,%26,%27,%28,%29,%30,%31}, [%32];"
        : "=r"(r[0]), "=r"(r[1]), "=r"(r[2]), "=r"(r[3]), "=r"(r[4]), "=r"(r[5]),
          "=r"(r[6]), "=r"(r[7]), "=r"(r[8]), "=r"(r[9]), "=r"(r[10]), "=r"(r[11]),
          "=r"(r[12]), "=r"(r[13]), "=r"(r[14]), "=r"(r[15]), "=r"(r[16]), "=r"(r[17]),
          "=r"(r[18]), "=r"(r[19]), "=r"(r[20]), "=r"(r[21]), "=r"(r[22]), "=r"(r[23]),
          "=r"(r[24]), "=r"(r[25]), "=r"(r[26]), "=r"(r[27]), "=r"(r[28]), "=r"(r[29]),
          "=r"(r[30]), "=r"(r[31])
        : "r"(ta));
#endif
}

// ---------------- argmax packing -------------------------------------------
__device__ __forceinline__ unsigned long long pack_key(float v, int idx) {
    unsigned u = __float_as_uint(v);
    u = (u & 0x80000000u) ? ~u : (u | 0x80000000u);
    return ((unsigned long long)u << 14) | (unsigned)(0x3FFF - idx);
}

// ---------------- split fp32 -> 2 x fp16, transposed to [lvl][p][k] --------
// B ONLY (A is split in-kernel by corr's prologue). 64k x 32p tiles; 16B
// coalesced half stores. y==0 blocks also zero g_best and g_cnt.
__global__ void split_kernel(const float* __restrict__ in, __half* __restrict__ out) {
    __shared__ float tile[64][33];
    const int pB = blockIdx.x * 32, kB = blockIdx.y * 64;
    const int t = threadIdx.x;            // 256
    const int tx = t & 31, ty = t >> 5;   // load mapping

    if (blockIdx.y == 0) {
        if (ty == 0) g_best[pB + tx] = 0ULL;
        if (t == 0) g_cnt[blockIdx.x / 4] = 0u;   // 384 blocks -> 96 counters (idempotent)
    }

    #pragma unroll
    for (int r = 0; r < 64; r += 8)
        tile[ty + r][tx] = in[(size_t)(kB + ty + r) * P + pB + tx];
    __syncthreads();

    // Each thread: one pixel p, 8 consecutive k -> one 16B store per level.
    const int p = t >> 3;
    const int ko = (t & 7) * 8;
    __half h0[8], h1[8];
    #pragma unroll
    for (int i = 0; i < 8; i++) {
        float x = tile[ko + i][p];
        __half a = __float2half_rn(x);
        float r1 = x - __half2float(a);
        h0[i] = a;
        h1[i] = __float2half_rn(r1);
    }
    size_t base = (size_t)(pB + p) * C + kB + ko;
    *(uint4*)&out[base] = *(uint4*)h0;
    *(uint4*)&out[(size_t)P * C + base] = *(uint4*)h1;
}

// ---------------- main GEMM + fused argmax + fused decode ---------------------
// grid (96,3), 416 threads. Warps 0-7 consumers, 8-11 loaders, 12 MMA issuer.
// fp16 2-split, 3 products. SS-mode, N=256 dispatches, 2-deep 64KB B ring.
// A is split fp32->2xfp16 IN the prologue (no global round-trip). D-ready is
// inferred from EMPTY(buf1) commits; consumers release D TMEM right after the
// last LDTM. Last CTA per m-tile decodes flow in-place.
__global__ __launch_bounds__(NTHREADS, 1) void corr_kernel(const float* __restrict__ A32,
                                                           const float* __restrict__ B32,
                                                           float* __restrict__ out,
                                                           const int* __restrict__ sxp,
                                                           const int* __restrict__ syp,
                                                           int has_scale) {
    extern __shared__ char smem[];
    const int tid = threadIdx.x;
    const int mBase = blockIdx.x * 128;
    const int rBase0 = blockIdx.y * NCHUNK;

#if HAS_TC
    // ======================= tcgen05 path =====================================
    const uint32_t sb = smem_u32(smem);
    const int wid = tid >> 5;

    if (wid == 12) tc_alloc(sb + SM_TMEM, 512u);
    if (tid == 0) {
        #pragma unroll
        for (int b = 0; b < 2; b++) {
            mbar_init(sb + MB_FULL + 8 * b, 128);
            mbar_init(sb + MB_EMPTY + 8 * b, 1);
        }
        mbar_init(sb + MB_E + 0, 8);
        mbar_init(sb + MB_E + 8, 8);
    }

    // ---- A prologue, fused split: fp32 tile -> h0/h1 swizzled smem tiles ----
    // Phase 1: coalesced load of A fp32 tile [128k][128m] into padded temp
    // (reuses the B-ring region, which is untouched until after __syncthreads).
    {
        float* atile = (float*)(smem + SM_B);     // [128][132] padded
        for (int e = tid; e < 128 * 128; e += NTHREADS) {
            int k = e >> 7, m = e & 127;
            atile[k * 132 + m] = A32[(size_t)k * P + mBase + m];
        }
        __syncthreads();
        // Phase 2: split + 16B swizzled stores (m-fast lane mapping:
        // stride-4B smem reads; swizzle spreads stores across bank quads).
        for (int e = tid; e < 2048; e += NTHREADS) {
            int m = e & 127, kq = e >> 7;
            __half h0[8], h1[8];
            #pragma unroll
            for (int i = 0; i < 8; i++) {
                float x = atile[(kq * 8 + i) * 132 + m];
                h0[i] = __float2half_rn(x);
                h1[i] = __float2half_rn(x - __half2float(h0[i]));
            }
            uint32_t off = swz(a_off(m, kq * 8));
            *(uint4*)(smem + SM_A + off) = *(uint4*)h0;
            *(uint4*)(smem + SM_A + 32768 + off) = *(uint4*)h1;
        }
    }
    fence_async();
    __syncthreads();

    uint32_t tmem;
    asm volatile("ld.shared.b32 %0, [%1];" : "=r"(tmem) : "r"(sb + SM_TMEM));

    if (wid >= 8 && wid < 12) {
        // -------- loaders: stream B chunks (tile-of-256, khalf) via cp.async ----
        const int tl = tid - 256;
        const int kq = tl & 7;                  // K 16B-quarter, fixed per thread
        const int row0 = tl >> 3;               // base row (0..15), step 16
        const __half* gb0 = g_Bsp + (size_t)rBase0 * C + kq * 8;

        int eph[2] = {1, 1};   // producer phase trick: first waits pass
        for (int ck = 0; ck < NCK; ck++) {
            const int buf = ck & 1;
            mbar_wait_rlx(sb + MB_EMPTY + 8 * buf, (uint32_t)eph[buf]);
            eph[buf] ^= 1;

            const size_t coff = (size_t)(ck >> 1) * (256 * C) + (size_t)(ck & 1) * 64;
            const uint32_t dl = sb + SM_B + buf * 65536;
            #pragma unroll
            for (int l = 0; l < 2; l++) {
                const __half* g = gb0 + (size_t)l * P * C + coff;
                #pragma unroll
                for (int j = 0; j < 16; j++) {
                    const int n = row0 + 16 * j;
                    cp_async16(dl + l * 32768 + swz((uint32_t)n * 128u + (uint32_t)kq * 16u),
                               g + (size_t)n * C);
                }
            }
            cp_commit();
            cp_wait0();
            fence_async();
            mbar_arrive(sb + MB_FULL + 8 * buf);
        }
    } else if (tid == 384) {
        // -------- dedicated MMA issuer (single thread of warp 12) --------------
        int fph[2] = {0, 0};
        int Eph[2] = {0, 0};
        uint64_t adesc[2];
        adesc[0] = mk_desc(sb + SM_A);
        adesc[1] = mk_desc(sb + SM_A + 32768);
        const int sa[3]  = {0, 0, 1};   // products: h0h0, h0h1, h1h0
        const int sbl[3] = {0, 1, 0};

        for (int ck = 0; ck < NCK; ck++) {
            const int buf = ck & 1, t = ck >> 1, kc = ck & 1;
            mbar_wait_rlx(sb + MB_FULL + 8 * buf, (uint32_t)fph[buf]);
            fph[buf] ^= 1;
            if (kc == 0 && t >= 2) {
                mbar_wait_rlx(sb + MB_E + 8 * (t & 1), (uint32_t)Eph[t & 1]);
                Eph[t & 1] ^= 1;
                tc_fence_after();
            }
            const uint32_t dt = tmem + TM_D + (t & 1) * 256;
            const uint32_t bb = sb + SM_B + buf * 65536;
            #pragma unroll
            for (int pr = 0; pr < 3; pr++) {
                uint64_t ad = adesc[sa[pr]];
                uint64_t bd = mk_desc(bb + sbl[pr] * 32768);
                #pragma unroll
                for (int ks = 0; ks < 4; ks++) {
                    const int s = kc * 4 + ks;
                    mma_f16_ss(dt, ad + (uint64_t)((s >> 2) * 1024 + (s & 3) * 2),
                               bd + (uint64_t)(ks * 2), IDESC,
                               !(kc == 0 && pr == 0 && ks == 0));
                }
            }
            // Single commit per chunk: frees the B buffer AND (for kc==1, i.e.
            // buf 1) tells consumers tile t's D is complete.
            tc_commit(sb + MB_EMPTY + 8 * buf);
        }
    } else if (wid < 8) {
        // -------- consumers: 8 warps; warp w = subpartition (w&3),
        // column half (w>>2)*128 of the 256-wide tile. 4 argmax chains. --------
        // D-ready for tile t = (t+1)-th firing of EMPTY(buf1) -> parity t&1.
        const int sp   = wid & 3;           // TMEM subpartition (= wid%4, HW rule)
        const int half = wid >> 2;          // 128-col half of the tile
        const int lane = tid & 31;
        const uint32_t woff = ((uint32_t)sp << 21) + (uint32_t)half * 128u;

        float bv[4];
        int   bi[4];
        #pragma unroll
        for (int c4 = 0; c4 < 4; c4++) { bv[c4] = -CUDART_INF_F; bi[c4] = 0; }

        for (int t = 0; t < NT; t++) {
            mbar_wait(sb + MB_EMPTY + 8, (uint32_t)(t & 1));
            tc_fence_after();
            const uint32_t dt = tmem + TM_D + (t & 1) * 256 + woff;
            const int colbase = rBase0 + t * 256 + half * 128;

            // q = 0
            {
                uint32_t r0[32], r1[32];
                ldtm_x32(r0, dt);
                ldtm_x32(r1, dt + 32);
                tc_wait_ld();
                #pragma unroll
                for (int j = 0; j < 32; j++) {
                    float v = __uint_as_float(r0[j]);
                    int c4 = j & 3;
                    if (v > bv[c4]) { bv[c4] = v; bi[c4] = colbase + j; }
                }
                #pragma unroll
                for (int j = 0; j < 32; j++) {
                    float v = __uint_as_float(r1[j]);
                    int c4 = j & 3;
                    if (v > bv[c4]) { bv[c4] = v; bi[c4] = colbase + 32 + j; }
                }
            }
            // q = 1: release the D buffer right after the data is in registers.
            {
                uint32_t r0[32], r1[32];
                ldtm_x32(r0, dt + 64);
                ldtm_x32(r1, dt + 96);
                tc_wait_ld();
                tc_fence_before();
                if (lane == 0) mbar_arrive(sb + MB_E + 8 * (t & 1));
                #pragma unroll
                for (int j = 0; j < 32; j++) {
                    float v = __uint_as_float(r0[j]);
                    int c4 = j & 3;
                    if (v > bv[c4]) { bv[c4] = v; bi[c4] = colbase + 64 + j; }
                }
                #pragma unroll
                for (int j = 0; j < 32; j++) {
                    float v = __uint_as_float(r1[j]);
                    int c4 = j & 3;
                    if (v > bv[c4]) { bv[c4] = v; bi[c4] = colbase + 96 + j; }
                }
            }
        }

        // Merge the 4 chains via packed keys (ties -> smallest index), then atomic.
        unsigned long long k0 = pack_key(bv[0], bi[0]);
        unsigned long long k1 = pack_key(bv[1], bi[1]);
        unsigned long long k2 = pack_key(bv[2], bi[2]);
        unsigned long long k3 = pack_key(bv[3], bi[3]);
        unsigned long long ka = (k0 > k1) ? k0 : k1;
        unsigned long long kb = (k2 > k3) ? k2 : k3;
        unsigned long long kk = (ka > kb) ? ka : kb;
        atomicMax(&g_best[mBase + sp * 32 + lane], kk);
    }

    __syncthreads();

#else
    // ======================= fallback (non-'a' compile pass only) ============
    // Compile-only safety net: correct but slow; the sm_103a pass is what runs.
    for (int r = 0; r < 128; r++) {
        float bv = -CUDART_INF_F;
        int bi = rBase0;
        for (int c = rBase0 + tid; c < rBase0 + NCHUNK; c += NTHREADS) {
            float dot = 0.0f;
            for (int k = 0; k < C; k++)
                dot = fmaf(A32[(size_t)k * P + mBase + r], B32[(size_t)k * P + c], dot);
            if (dot > bv) { bv = dot; bi = c; }
        }
        atomicMax(&g_best[mBase + r], pack_key(bv, bi));
    }
    __syncthreads();
#endif

    // ---------- fused decode: last CTA (of NSPL) per m-tile decodes it -------
    int* lastf = (int*)(smem + SM_LAST);
    if (tid == 0) {
        __threadfence();
        unsigned old = atomicAdd(&g_cnt[blockIdx.x], 1u);
        *lastf = (old == NSPL - 1) ? 1 : 0;
    }
    __syncthreads();
    if (*lastf && tid < 128) {
        const int sx = has_scale ? sxp[0] : 4;
        const int sy = has_scale ? syp[0] : 4;
        const int p = mBase + tid;
        unsigned long long pk = __ldcg(&g_best[p]);
        int idx = 0x3FFF - (int)(pk & 0x3FFFULL);
        unsigned u = (unsigned)(pk >> 14);
        unsigned f = (u & 0x80000000u) ? (u ^ 0x80000000u) : ~u;
        float val = __uint_as_float(f);
        int h = p >> 7, w = p & 127;
        int i = idx >> 7, j = idx & 127;
        out[2 * p]     = (float)(w - j * sx);
        out[2 * p + 1] = (float)(h - i * sy);
        out[2 * P + p] = val;
    }

#if HAS_TC
    if ((tid >> 5) == 12) {
        uint32_t tmem2;
        asm volatile("ld.shared.b32 %0, [%1];" : "=r"(tmem2) : "r"(smem_u32(smem) + SM_TMEM));
        tc_dealloc(tmem2, 512u);
    }
#endif
}

// ---------------- launch -----------------------------------------------------
extern "C" void kernel_launch(void* const* d_in, const int* in_sizes, int n_in,
                              void* d_out, int out_size) {
    const float* A = (const float*)d_in[0];
    const float* B = (const float*)d_in[1];
    const int* sx = (n_in > 2) ? (const int*)d_in[2] : nullptr;
    const int* sy = (n_in > 3) ? (const int*)d_in[3] : nullptr;
    int has_scale = (n_in > 3) ? 1 : 0;

    cudaFuncSetAttribute(corr_kernel, cudaFuncAttributeMaxDynamicSharedMemorySize, SMEM_TOTAL);

    __half* dBs;
    cudaGetSymbolAddress((void**)&dBs, g_Bsp);

    dim3 sgrid(P / 32, C / 64), sblk(256);
    split_kernel<<<sgrid, sblk>>>(B, dBs);   // B only; also zeroes g_best/g_cnt

    dim3 grid(P / 128, NSPL);   // 96 x 3 = 288 CTAs
    corr_kernel<<<grid, NTHREADS, SMEM_TOTAL>>>(A, B, (float*)d_out, sx, sy, has_scale);
}

// round 17
// speedup vs baseline: 1.0716x; 1.0490x over previous
#include <cuda_runtime.h>
#include <cuda_fp16.h>
#include <math_constants.h>
#include <cstdint>

#define C 128
#define H 96
#define W 128
#define P (H * W)            // 12288
#define NSPL 3
#define NCHUNK (P / NSPL)    // 4096
#define NT (NCHUNK / 256)    // 16 N-tiles (of 256) per CTA
#define NCK (NT * 2)         // 32 chunks: (tile, khalf)
#define IDESC 0x8400010u     // f32 accum, fp16 x fp16, N=256, M=128 (cg1)
#define NTHREADS 416         // warps 0-7 consumers, 8-11 loaders, 12 MMA

// tcgen05 is an arch-SPECIFIC feature: only valid when compiling for sm_103a.
#if defined(__CUDA_ARCH__) && defined(__CUDA_ARCH_FEAT_SM103_ALL)
#define HAS_TC 1
#else
#define HAS_TC 0
#endif

// ---------------- device globals (scratch; no allocation allowed) ----------
__device__ unsigned long long g_best[P];
__device__ unsigned g_cnt[P / 128];      // per-m-tile completion counters
__device__ __half g_Asp[2ull * P * C];   // [lvl][pixel][channel]
__device__ __half g_Bsp[2ull * P * C];

// ---------------- smem layout (dynamic) ------------------------------------
#define SM_TMEM  0
#define MB_FULL  16      // 2 x 8B  (loaders -> MMA, count=128)
#define MB_EMPTY 32      // 2 x 8B  (MMA commit -> loaders AND consumers, count=1)
#define MB_E     64      // 2 x 8B  (consumers -> MMA, count=8)
#define SM_LAST  112     // 4B flag: this CTA decodes its m-tile
#define SM_B     1024                     // 2 bufs x 65536 (2 lvls x 256rows x 128B)
#define SM_A     (SM_B + 2 * 65536)       // 2 lvls x 32768
#define SMEM_TOTAL (SM_A + 2 * 32768)     // 197632 bytes

// TMEM: D double buffer at cols 0 / 256 (256 cols each).
#define TM_D 0

// ---------------- PTX helpers ----------------------------------------------
__device__ __forceinline__ uint32_t smem_u32(const void* p) {
    uint32_t a;
    asm("{ .reg .u64 t; cvta.to.shared.u64 t, %1; cvt.u32.u64 %0, t; }"
        : "=r"(a) : "l"(p));
    return a;
}
__device__ __forceinline__ uint32_t swz(uint32_t b) { return b ^ ((b >> 3) & 0x70); }
__device__ __forceinline__ uint32_t a_off(int m, int k) {
    // blocked atom layout: atom = 8 rows x 64 fp16 (1024B); 16 atom-rows x 2 atom-cols
    return ((uint32_t)((m >> 3) + (k >> 6) * 16)) * 1024u + (uint32_t)(m & 7) * 128u
         + (uint32_t)(k & 63) * 2u;
}
__device__ __forceinline__ uint64_t mk_desc(uint32_t addr) {
    // SW128, Blackwell version=1, LBO=1, SBO=64 (K-major)
    return ((uint64_t)2 << 61) | ((uint64_t)1 << 46) | ((uint64_t)64 << 32)
         | ((uint64_t)1 << 16) | ((addr >> 4) & 0x3FFF);
}

__device__ __forceinline__ void cp_async16(uint32_t dst, const void* src) {
    asm volatile("cp.async.cg.shared.global [%0], [%1], 16;"
                 :: "r"(dst), "l"(src) : "memory");
}
__device__ __forceinline__ void cp_commit() {
    asm volatile("cp.async.commit_group;" ::: "memory");
}
__device__ __forceinline__ void cp_wait0() {
    asm volatile("cp.async.wait_group 0;" ::: "memory");
}

__device__ __forceinline__ void mbar_init(uint32_t a, uint32_t n) {
#if HAS_TC
    asm volatile("mbarrier.init.shared.b64 [%0], %1;" :: "r"(a), "r"(n) : "memory");
#endif
}
__device__ __forceinline__ void mbar_arrive(uint32_t a) {
#if HAS_TC
    asm volatile("mbarrier.arrive.shared.b64 _, [%0];" :: "r"(a) : "memory");
#endif
}
__device__ __forceinline__ void tc_commit(uint32_t a) {
#if HAS_TC
    asm volatile("tcgen05.commit.cta_group::1.mbarrier::arrive::one.shared::cluster.b64 [%0];"
                 :: "r"(a) : "memory");
#endif
}
__device__ __forceinline__ void tc_fence_after()  {
#if HAS_TC
    asm volatile("tcgen05.fence::after_thread_sync;" ::: "memory");
#endif
}
__device__ __forceinline__ void tc_fence_before() {
#if HAS_TC
    asm volatile("tcgen05.fence::before_thread_sync;" ::: "memory");
#endif
}
__device__ __forceinline__ void tc_wait_ld() {
#if HAS_TC
    asm volatile("tcgen05.wait::ld.sync.aligned;" ::: "memory");
#endif
}
__device__ __forceinline__ void fence_async() {
#if HAS_TC
    asm volatile("fence.proxy.async.shared::cta;" ::: "memory");
#endif
}
__device__ __forceinline__ void tc_alloc(uint32_t dst, uint32_t ncols) {
#if HAS_TC
    asm volatile("tcgen05.alloc.cta_group::1.sync.aligned.shared::cta.b32 [%0], %1;"
                 :: "r"(dst), "r"(ncols) : "memory");
#endif
}
__device__ __forceinline__ void tc_dealloc(uint32_t tmem, uint32_t ncols) {
#if HAS_TC
    asm volatile("tcgen05.relinquish_alloc_permit.cta_group::1.sync.aligned;");
    asm volatile("tcgen05.dealloc.cta_group::1.sync.aligned.b32 %0, %1;"
                 :: "r"(tmem), "r"(ncols));
#endif
}
// Acquire wait (consumers: generic LDTM follows).
__device__ __forceinline__ void mbar_wait(uint32_t mbar, uint32_t parity) {
#if HAS_TC
    uint32_t done;
    asm volatile(
        "{\n\t.reg .pred p;\n\t"
        "mbarrier.try_wait.parity.acquire.cta.shared::cta.b64 p, [%1], %2;\n\t"
        "selp.b32 %0, 1, 0, p;\n\t}"
        : "=r"(done) : "r"(mbar), "r"(parity) : "memory");
    if (!done) {
        asm volatile(
            "{\n\t.reg .pred P1;\n\t"
            "W_%=:\n\t"
            "mbarrier.try_wait.parity.acquire.cta.shared::cta.b64 P1, [%0], %1, 0x989680;\n\t"
            "@P1 bra.uni D_%=;\n\t"
            "bra.uni W_%=;\n\t"
            "D_%=:\n\t}"
            :: "r"(mbar), "r"(parity) : "memory");
    }
#endif
}
// Relaxed wait (issuer/loaders: post-wait accesses are async-proxy only).
__device__ __forceinline__ void mbar_wait_rlx(uint32_t mbar, uint32_t parity) {
#if HAS_TC
    uint32_t done;
    asm volatile(
        "{\n\t.reg .pred p;\n\t"
        "mbarrier.try_wait.parity.relaxed.cta.shared::cta.b64 p, [%1], %2;\n\t"
        "selp.b32 %0, 1, 0, p;\n\t}"
        : "=r"(done) : "r"(mbar), "r"(parity) : "memory");
    if (!done) {
        asm volatile(
            "{\n\t.reg .pred P1;\n\t"
            "W_%=:\n\t"
            "mbarrier.try_wait.parity.relaxed.cta.shared::cta.b64 P1, [%0], %1, 0x989680;\n\t"
            "@P1 bra.uni D_%=;\n\t"
            "bra.uni W_%=;\n\t"
            "D_%=:\n\t}"
            :: "r"(mbar), "r"(parity) : "memory");
    }
#endif
}
__device__ __forceinline__ void mma_f16_ss(uint32_t d, uint64_t ad, uint64_t bd,
                                           uint32_t idesc, bool en) {
#if HAS_TC
    uint32_t e = en ? 1u : 0u;
    asm volatile(
        "{\n\t.reg .pred p;\n\tsetp.ne.u32 p, %5, 0;\n\t"
        "tcgen05.mma.cta_group::1.kind::f16 [%0], %1, %2, %3, {%4,%4,%4,%4}, p;\n\t}"
        :: "r"(d), "l"(ad), "l"(bd), "r"(idesc), "r"(0u), "r"(e) : "memory");
#endif
}
__device__ __forceinline__ void ldtm_x32(uint32_t* r, uint32_t ta) {
#if HAS_TC
    asm volatile(
        "tcgen05.ld.sync.aligned.32x32b.x32.b32 "
        "{%0,%1,%2,%3,%4,%5,%6,%7,%8,%9,%10,%11,%12,%13,%14,%15,"
        "%16,%17,%18,%19,%20,%21,%22,%23,%24,%25,%26,%27,%28,%29,%30,%31}, [%32];"
        : "=r"(r[0]), "=r"(r[1]), "=r"(r[2]), "=r"(r[3]), "=r"(r[4]), "=r"(r[5]),
          "=r"(r[6]), "=r"(r[7]), "=r"(r[8]), "=r"(r[9]), "=r"(r[10]), "=r"(r[11]),
          "=r"(r[12]), "=r"(r[13]), "=r"(r[14]), "=r"(r[15]), "=r"(r[16]), "=r"(r[17]),
          "=r"(r[18]), "=r"(r[19]), "=r"(r[20]), "=r"(r[21]), "=r"(r[22]), "=r"(r[23]),
          "=r"(r[24]), "=r"(r[25]), "=r"(r[26]), "=r"(r[27]), "=r"(r[28]), "=r"(r[29]),
          "=r"(r[30]), "=r"(r[31])
        : "r"(ta));
#endif
}

// ---------------- argmax packing -------------------------------------------
__device__ __forceinline__ unsigned long long pack_key(float v, int idx) {
    unsigned u = __float_as_uint(v);
    u = (u & 0x80000000u) ? ~u : (u | 0x80000000u);
    return ((unsigned long long)u << 14) | (unsigned)(0x3FFF - idx);
}

// ---------------- split fp32 -> 2 x fp16, transposed to [lvl][p][k] --------
// 64k x 32p tiles; 16B coalesced half stores. z selects (A,B).
// z==0/y==0 blocks also zero g_best and g_cnt (runs before corr_kernel).
__global__ void split_kernel(const float* __restrict__ inA, const float* __restrict__ inB,
                             __half* __restrict__ outA, __half* __restrict__ outB) {
    __shared__ float tile[64][33];
    const float* in = (blockIdx.z == 0) ? inA : inB;
    __half* out = (blockIdx.z == 0) ? outA : outB;
    const int pB = blockIdx.x * 32, kB = blockIdx.y * 64;
    const int t = threadIdx.x;            // 256
    const int tx = t & 31, ty = t >> 5;   // load mapping

    if (blockIdx.z == 0 && blockIdx.y == 0) {
        if (ty == 0) g_best[pB + tx] = 0ULL;
        if (t == 0) g_cnt[blockIdx.x / 4] = 0u;   // 384 blocks -> 96 counters (idempotent)
    }

    #pragma unroll
    for (int r = 0; r < 64; r += 8)
        tile[ty + r][tx] = in[(size_t)(kB + ty + r) * P + pB + tx];
    __syncthreads();

    // Each thread: one pixel p, 8 consecutive k -> one 16B store per level.
    const int p = t >> 3;
    const int ko = (t & 7) * 8;
    __half h0[8], h1[8];
    #pragma unroll
    for (int i = 0; i < 8; i++) {
        float x = tile[ko + i][p];
        __half a = __float2half_rn(x);
        float r1 = x - __half2float(a);
        h0[i] = a;
        h1[i] = __float2half_rn(r1);
    }
    size_t base = (size_t)(pB + p) * C + kB + ko;
    *(uint4*)&out[base] = *(uint4*)h0;
    *(uint4*)&out[(size_t)P * C + base] = *(uint4*)h1;
}

// ---------------- main GEMM + fused argmax + fused decode ---------------------
// grid (96,3), 416 threads. Warps 0-7 consumers, 8-11 loaders, 12 MMA issuer.
// fp16 2-split, 3 products. SS-mode, N=256 dispatches, 2-deep 64KB B ring.
// Loaders start streaming B IMMEDIATELY (overlapping the A prologue, which is
// done by warps 0-7 + 12 and ordered against the issuer via bar.sync 1,288).
// D-ready is inferred from EMPTY(buf1) commits; consumers release D TMEM right
// after the last LDTM. Last CTA per m-tile decodes flow in-place.
__global__ __launch_bounds__(NTHREADS, 1) void corr_kernel(const float* __restrict__ A32,
                                                           const float* __restrict__ B32,
                                                           float* __restrict__ out,
                                                           const int* __restrict__ sxp,
                                                           const int* __restrict__ syp,
                                                           int has_scale) {
    extern __shared__ char smem[];
    const int tid = threadIdx.x;
    const int mBase = blockIdx.x * 128;
    const int rBase0 = blockIdx.y * NCHUNK;

#if HAS_TC
    // ======================= tcgen05 path =====================================
    const uint32_t sb = smem_u32(smem);
    const int wid = tid >> 5;

    if (wid == 12) tc_alloc(sb + SM_TMEM, 512u);
    if (tid == 0) {
        #pragma unroll
        for (int b = 0; b < 2; b++) {
            mbar_init(sb + MB_FULL + 8 * b, 128);
            mbar_init(sb + MB_EMPTY + 8 * b, 1);
        }
        mbar_init(sb + MB_E + 0, 8);
        mbar_init(sb + MB_E + 8, 8);
    }
    // Early cheap sync: barriers + TMEM ptr visible to ALL warps; nothing else
    // is pending, so this costs ~BAR floor only.
    __syncthreads();

    uint32_t tmem;
    asm volatile("ld.shared.b32 %0, [%1];" : "=r"(tmem) : "r"(sb + SM_TMEM));

    if (wid >= 8 && wid < 12) {
        // -------- loaders: start streaming B chunks IMMEDIATELY ----------------
        const int tl = tid - 256;
        const int kq = tl & 7;                  // K 16B-quarter, fixed per thread
        const int row0 = tl >> 3;               // base row (0..15), step 16
        const __half* gb0 = g_Bsp + (size_t)rBase0 * C + kq * 8;

        int eph[2] = {1, 1};   // producer phase trick: first waits pass
        for (int ck = 0; ck < NCK; ck++) {
            const int buf = ck & 1;
            mbar_wait_rlx(sb + MB_EMPTY + 8 * buf, (uint32_t)eph[buf]);
            eph[buf] ^= 1;

            const size_t coff = (size_t)(ck >> 1) * (256 * C) + (size_t)(ck & 1) * 64;
            const uint32_t dl = sb + SM_B + buf * 65536;
            #pragma unroll
            for (int l = 0; l < 2; l++) {
                const __half* g = gb0 + (size_t)l * P * C + coff;
                #pragma unroll
                for (int j = 0; j < 16; j++) {
                    const int n = row0 + 16 * j;
                    cp_async16(dl + l * 32768 + swz((uint32_t)n * 128u + (uint32_t)kq * 16u),
                               g + (size_t)n * C);
                }
            }
            cp_commit();
            cp_wait0();
            fence_async();
            mbar_arrive(sb + MB_FULL + 8 * buf);
        }
    } else {
        // -------- A prologue (warps 0-7 + 12, overlapped with B chunk 0) -------
        const int pe = (tid < 256) ? tid : (tid - 128);   // 0..287
        for (int e = pe; e < 4096; e += 288) {
            int kq16 = e & 15, m = (e >> 4) & 127, lvl = e >> 11;
            const __half* src = g_Asp + (size_t)lvl * P * C
                              + (size_t)(mBase + m) * C + kq16 * 8;
            cp_async16(sb + SM_A + lvl * 32768 + swz(a_off(m, kq16 * 8)), src);
        }
        cp_commit();
        cp_wait0();
        fence_async();
        asm volatile("bar.sync 1, 288;" ::: "memory");   // A ready for issuer

        if (tid == 384) {
            // -------- dedicated MMA issuer (single thread of warp 12) ----------
            int fph[2] = {0, 0};
            int Eph[2] = {0, 0};
            uint64_t adesc[2];
            adesc[0] = mk_desc(sb + SM_A);
            adesc[1] = mk_desc(sb + SM_A + 32768);
            const int sa[3]  = {0, 0, 1};   // products: h0h0, h0h1, h1h0
            const int sbl[3] = {0, 1, 0};

            for (int ck = 0; ck < NCK; ck++) {
                const int buf = ck & 1, t = ck >> 1, kc = ck & 1;
                mbar_wait_rlx(sb + MB_FULL + 8 * buf, (uint32_t)fph[buf]);
                fph[buf] ^= 1;
                if (kc == 0 && t >= 2) {
                    mbar_wait_rlx(sb + MB_E + 8 * (t & 1), (uint32_t)Eph[t & 1]);
                    Eph[t & 1] ^= 1;
                    tc_fence_after();
                }
                const uint32_t dt = tmem + TM_D + (t & 1) * 256;
                const uint32_t bb = sb + SM_B + buf * 65536;
                #pragma unroll
                for (int pr = 0; pr < 3; pr++) {
                    uint64_t ad = adesc[sa[pr]];
                    uint64_t bd = mk_desc(bb + sbl[pr] * 32768);
                    #pragma unroll
                    for (int ks = 0; ks < 4; ks++) {
                        const int s = kc * 4 + ks;
                        mma_f16_ss(dt, ad + (uint64_t)((s >> 2) * 1024 + (s & 3) * 2),
                                   bd + (uint64_t)(ks * 2), IDESC,
                                   !(kc == 0 && pr == 0 && ks == 0));
                    }
                }
                // Single commit per chunk: frees the B buffer AND (for kc==1,
                // i.e. buf 1) tells consumers tile t's D is complete.
                tc_commit(sb + MB_EMPTY + 8 * buf);
            }
        } else if (wid < 8) {
            // -------- consumers: 8 warps; warp w = subpartition (w&3),
            // column half (w>>2)*128 of the 256-wide tile. 4 argmax chains. ----
            // D-ready for tile t = (t+1)-th firing of EMPTY(buf1) -> parity t&1.
            const int sp   = wid & 3;       // TMEM subpartition (= wid%4, HW rule)
            const int half = wid >> 2;      // 128-col half of the tile
            const int lane = tid & 31;
            const uint32_t woff = ((uint32_t)sp << 21) + (uint32_t)half * 128u;

            float bv[4];
            int   bi[4];
            #pragma unroll
            for (int c4 = 0; c4 < 4; c4++) { bv[c4] = -CUDART_INF_F; bi[c4] = 0; }

            for (int t = 0; t < NT; t++) {
                mbar_wait(sb + MB_EMPTY + 8, (uint32_t)(t & 1));
                tc_fence_after();
                const uint32_t dt = tmem + TM_D + (t & 1) * 256 + woff;
                const int colbase = rBase0 + t * 256 + half * 128;

                // q = 0
                {
                    uint32_t r0[32], r1[32];
                    ldtm_x32(r0, dt);
                    ldtm_x32(r1, dt + 32);
                    tc_wait_ld();
                    #pragma unroll
                    for (int j = 0; j < 32; j++) {
                        float v = __uint_as_float(r0[j]);
                        int c4 = j & 3;
                        if (v > bv[c4]) { bv[c4] = v; bi[c4] = colbase + j; }
                    }
                    #pragma unroll
                    for (int j = 0; j < 32; j++) {
                        float v = __uint_as_float(r1[j]);
                        int c4 = j & 3;
                        if (v > bv[c4]) { bv[c4] = v; bi[c4] = colbase + 32 + j; }
                    }
                }
                // q = 1: release the D buffer right after data is in registers.
                {
                    uint32_t r0[32], r1[32];
                    ldtm_x32(r0, dt + 64);
                    ldtm_x32(r1, dt + 96);
                    tc_wait_ld();
                    tc_fence_before();
                    if (lane == 0) mbar_arrive(sb + MB_E + 8 * (t & 1));
                    #pragma unroll
                    for (int j = 0; j < 32; j++) {
                        float v = __uint_as_float(r0[j]);
                        int c4 = j & 3;
                        if (v > bv[c4]) { bv[c4] = v; bi[c4] = colbase + 64 + j; }
                    }
                    #pragma unroll
                    for (int j = 0; j < 32; j++) {
                        float v = __uint_as_float(r1[j]);
                        int c4 = j & 3;
                        if (v > bv[c4]) { bv[c4] = v; bi[c4] = colbase + 96 + j; }
                    }
                }
            }

            // Merge the 4 chains via packed keys (ties -> smallest index).
            unsigned long long k0 = pack_key(bv[0], bi[0]);
            unsigned long long k1 = pack_key(bv[1], bi[1]);
            unsigned long long k2 = pack_key(bv[2], bi[2]);
            unsigned long long k3 = pack_key(bv[3], bi[3]);
            unsigned long long ka = (k0 > k1) ? k0 : k1;
            unsigned long long kb = (k2 > k3) ? k2 : k3;
            unsigned long long kk = (ka > kb) ? ka : kb;
            atomicMax(&g_best[mBase + sp * 32 + lane], kk);
        }
    }

    __syncthreads();

#else
    // ======================= fallback (non-'a' compile pass only) ============
    // Compile-only safety net: correct but slow; the sm_103a pass is what runs.
    for (int r = 0; r < 128; r++) {
        float bv = -CUDART_INF_F;
        int bi = rBase0;
        for (int c = rBase0 + tid; c < rBase0 + NCHUNK; c += NTHREADS) {
            float dot = 0.0f;
            for (int k = 0; k < C; k++)
                dot = fmaf(A32[(size_t)k * P + mBase + r], B32[(size_t)k * P + c], dot);
            if (dot > bv) { bv = dot; bi = c; }
        }
        atomicMax(&g_best[mBase + r], pack_key(bv, bi));
    }
    __syncthreads();
#endif

    // ---------- fused decode: last CTA (of NSPL) per m-tile decodes it -------
    int* lastf = (int*)(smem + SM_LAST);
    if (tid == 0) {
        __threadfence();
        unsigned old = atomicAdd(&g_cnt[blockIdx.x], 1u);
        *lastf = (old == NSPL - 1) ? 1 : 0;
    }
    __syncthreads();
    if (*lastf && tid < 128) {
        const int sx = has_scale ? sxp[0] : 4;
        const int sy = has_scale ? syp[0] : 4;
        const int p = mBase + tid;
        unsigned long long pk = __ldcg(&g_best[p]);
        int idx = 0x3FFF - (int)(pk & 0x3FFFULL);
        unsigned u = (unsigned)(pk >> 14);
        unsigned f = (u & 0x80000000u) ? (u ^ 0x80000000u) : ~u;
        float val = __uint_as_float(f);
        int h = p >> 7, w = p & 127;
        int i = idx >> 7, j = idx & 127;
        out[2 * p]     = (float)(w - j * sx);
        out[2 * p + 1] = (float)(h - i * sy);
        out[2 * P + p] = val;
    }

#if HAS_TC
    if ((tid >> 5) == 12) {
        uint32_t tmem2;
        asm volatile("ld.shared.b32 %0, [%1];" : "=r"(tmem2) : "r"(smem_u32(smem) + SM_TMEM));
        tc_dealloc(tmem2, 512u);
    }
#endif
}

// ---------------- launch -----------------------------------------------------
extern "C" void kernel_launch(void* const* d_in, const int* in_sizes, int n_in,
                              void* d_out, int out_size) {
    const float* A = (const float*)d_in[0];
    const float* B = (const float*)d_in[1];
    const int* sx = (n_in > 2) ? (const int*)d_in[2] : nullptr;
    const int* sy = (n_in > 3) ? (const int*)d_in[3] : nullptr;
    int has_scale = (n_in > 3) ? 1 : 0;

    cudaFuncSetAttribute(corr_kernel, cudaFuncAttributeMaxDynamicSharedMemorySize, SMEM_TOTAL);

    __half* dAs;
    __half* dBs;
    cudaGetSymbolAddress((void**)&dAs, g_Asp);
    cudaGetSymbolAddress((void**)&dBs, g_Bsp);

    dim3 sgrid(P / 32, C / 64, 2), sblk(256);
    split_kernel<<<sgrid, sblk>>>(A, B, dAs, dBs);   // also zeroes g_best/g_cnt

    dim3 grid(P / 128, NSPL);   // 96 x 3 = 288 CTAs
    corr_kernel<<<grid, NTHREADS, SMEM_TOTAL>>>(A, B, (float*)d_out, sx, sy, has_scale);
}